// round 5
// baseline (speedup 1.0000x reference)
#include <cuda_runtime.h>
#include <math.h>
#include <stdint.h>

#define N_TOKENS 16384
#define D_MODEL  1024
#define D_FF     2048
#define N_EXPERTS 4

// ---------------- scratch (device globals; no allocation allowed) ----------------
__device__ int   g_cnt[N_EXPERTS];
__device__ int   g_tok[N_EXPERTS * N_TOKENS];
__device__ float g_wgt[N_EXPERTS * N_TOKENS];
__device__ float g_H[(size_t)N_EXPERTS * N_TOKENS * D_FF];     // 512 MB
__device__ float g_Z[(size_t)N_EXPERTS * N_TOKENS * D_MODEL];  // 256 MB

__device__ __forceinline__ float gelu_exact(float v) {
    return 0.5f * v * (1.0f + erff(v * 0.70710678118654752440f));
}

__device__ __forceinline__ void mma_tf32(float c[4], const uint32_t a[4], const uint32_t b[2]) {
    asm volatile(
        "mma.sync.aligned.m16n8k8.row.col.f32.tf32.tf32.f32 "
        "{%0,%1,%2,%3}, {%4,%5,%6,%7}, {%8,%9}, {%0,%1,%2,%3};"
        : "+f"(c[0]), "+f"(c[1]), "+f"(c[2]), "+f"(c[3])
        : "r"(a[0]), "r"(a[1]), "r"(a[2]), "r"(a[3]), "r"(b[0]), "r"(b[1]));
}

__device__ __forceinline__ uint32_t smem_u32(const void* p) {
    uint32_t a;
    asm("{ .reg .u64 t; cvta.to.shared.u64 t, %1; cvt.u32.u64 %0, t; }" : "=r"(a) : "l"(p));
    return a;
}
__device__ __forceinline__ void cpasync16(uint32_t dst, const void* src) {
    asm volatile("cp.async.cg.shared.global [%0], [%1], 16;" :: "r"(dst), "l"(src));
}
__device__ __forceinline__ void cp_commit() {
    asm volatile("cp.async.commit_group;" ::: "memory");
}
__device__ __forceinline__ void cp_wait1() {
    asm volatile("cp.async.wait_group 1;" ::: "memory");
}
__device__ __forceinline__ void cp_wait0() {
    asm volatile("cp.async.wait_group 0;" ::: "memory");
}

// ---------------- init ----------------
__global__ void init_counts_kernel() {
    if (threadIdx.x < N_EXPERTS) g_cnt[threadIdx.x] = 0;
}

// ---------------- gating: scores, top-2, softmax, compaction ----------------
__global__ void __launch_bounds__(256) gate_kernel(const float* __restrict__ x,
                                                   const float* __restrict__ gate_w) {
    __shared__ float sgw[N_EXPERTS * D_MODEL];
    const int tid = threadIdx.x;
    for (int i = tid; i < N_EXPERTS * D_MODEL; i += 256) sgw[i] = gate_w[i];
    __syncthreads();

    const int warp = tid >> 5, lane = tid & 31;
    const int tok = blockIdx.x * 8 + warp;
    if (tok >= N_TOKENS) return;

    const float* xr = x + (size_t)tok * D_MODEL;
    float acc0 = 0.f, acc1 = 0.f, acc2 = 0.f, acc3 = 0.f;
    for (int k = lane; k < D_MODEL; k += 32) {
        float xv = xr[k];
        acc0 += xv * sgw[0 * D_MODEL + k];
        acc1 += xv * sgw[1 * D_MODEL + k];
        acc2 += xv * sgw[2 * D_MODEL + k];
        acc3 += xv * sgw[3 * D_MODEL + k];
    }
    #pragma unroll
    for (int o = 16; o; o >>= 1) {
        acc0 += __shfl_xor_sync(0xffffffffu, acc0, o);
        acc1 += __shfl_xor_sync(0xffffffffu, acc1, o);
        acc2 += __shfl_xor_sync(0xffffffffu, acc2, o);
        acc3 += __shfl_xor_sync(0xffffffffu, acc3, o);
    }
    if (lane == 0) {
        float s[4] = {acc0, acc1, acc2, acc3};
        int i0 = 0;
        #pragma unroll
        for (int e = 1; e < 4; e++) if (s[e] > s[i0]) i0 = e;
        int i1 = -1;
        #pragma unroll
        for (int e = 0; e < 4; e++) {
            if (e == i0) continue;
            if (i1 < 0 || s[e] > s[i1]) i1 = e;
        }
        float t  = expf(s[i1] - s[i0]);
        float p0 = 1.0f / (1.0f + t);
        float p1 = t / (1.0f + t);

        int p = atomicAdd(&g_cnt[i0], 1);
        g_tok[i0 * N_TOKENS + p] = tok;
        g_wgt[i0 * N_TOKENS + p] = p0;
        p = atomicAdd(&g_cnt[i1], 1);
        g_tok[i1 * N_TOKENS + p] = tok;
        g_wgt[i1 * N_TOKENS + p] = p1;
    }
}

// ======================= TF32 tensor-core GEMMs (cp.async pipelined) =======================
// Tile 128(M) x 256(N), BK=32, 256 threads = 8 warps (2 M x 4 N), warp tile 64x64.
// 3-stage cp.async pipeline, smem row stride 36 floats (conflict-free fragment LDS).
#define BK 32
#define SROW 36
#define STAGES 3
#define BN 256
#define A_STAGE_F (128 * SROW)                 // 4608 floats
#define B_STAGE_F (BN  * SROW)                 // 9216 floats
#define STAGE_F   (A_STAGE_F + B_STAGE_F)      // 13824 floats
#define SMEM_DYN  (STAGES * STAGE_F * 4)       // 165888 bytes

template<int KDIM, bool G1>
__global__ void __launch_bounds__(256, 1) moe_gemm(
    const float* __restrict__ Asrc, const float* __restrict__ W,
    const float* __restrict__ bias, const float* __restrict__ resid)
{
    const int e   = blockIdx.z;
    const int cnt = g_cnt[e];
    const int m0  = blockIdx.y * 128;
    if (m0 >= cnt) return;
    const int n0  = blockIdx.x * BN;

    extern __shared__ float smem[];
    __shared__ int stok[128];

    const int tid = threadIdx.x;
    if (tid < 128) {
        int m = m0 + tid;
        stok[tid] = g_tok[e * N_TOKENS + (m < cnt ? m : cnt - 1)];
    }
    __syncthreads();

    // ---- loader mapping: per stage, per thread: 4 A-chunks + 8 B-chunks of 16B ----
    const int cj4  = (tid & 7) * 4;   // float offset within a 32-float row
    const int row0 = tid >> 3;        // 0..31

    const float* aptr[4];
    const float* bptr[8];
    uint32_t aoff16[4], boff16[8];
    #pragma unroll
    for (int i = 0; i < 4; i++) {
        const int row = row0 + 32 * i;
        if (G1) {
            aptr[i] = Asrc + (size_t)stok[row] * KDIM + cj4;
        } else {
            int mr = m0 + row; if (mr >= cnt) mr = cnt - 1;
            aptr[i] = Asrc + ((size_t)e * N_TOKENS + mr) * KDIM + cj4;
        }
        aoff16[i] = (uint32_t)(row * SROW + cj4) * 4u;
    }
    #pragma unroll
    for (int i = 0; i < 8; i++) {
        const int row = row0 + 32 * i;
        bptr[i] = W + (size_t)e * ((size_t)D_FF * D_MODEL) + (size_t)(n0 + row) * KDIM + cj4;
        boff16[i] = (uint32_t)(A_STAGE_F + row * SROW + cj4) * 4u;
    }

    const uint32_t sbase = smem_u32(smem);

    auto issue = [&](int t, int s) {
        const int kt = t * BK;
        const uint32_t sa = sbase + (uint32_t)s * (STAGE_F * 4);
        #pragma unroll
        for (int i = 0; i < 4; i++) cpasync16(sa + aoff16[i], aptr[i] + kt);
        #pragma unroll
        for (int i = 0; i < 8; i++) cpasync16(sa + boff16[i], bptr[i] + kt);
    };

    // ---- compute mapping: 8 warps = 2 (M) x 4 (N), warp tile 64x64 ----
    const int warp = tid >> 5, lane = tid & 31;
    const int wm = (warp & 1) * 64;
    const int wn = (warp >> 1) * 64;
    const int gid = lane >> 2, tig = lane & 3;

    float acc[4][8][4];
    #pragma unroll
    for (int mt = 0; mt < 4; mt++)
        #pragma unroll
        for (int nt = 0; nt < 8; nt++)
            #pragma unroll
            for (int r = 0; r < 4; r++) acc[mt][nt][r] = 0.f;

    constexpr int T = KDIM / BK;

    issue(0, 0); cp_commit();
    issue(1, 1); cp_commit();

    for (int t = 0; t < T; t++) {
        const int s = t % STAGES;
        if (t + 2 < T) cp_wait1(); else cp_wait0();
        __syncthreads();
        if (t + 2 < T) { issue(t + 2, (t + 2) % STAGES); cp_commit(); }

        const float* As = smem + s * STAGE_F;
        const float* Bs = As + A_STAGE_F;

        #pragma unroll
        for (int ks = 0; ks < 4; ks++) {
            const int kc = ks * 8 + tig;
            uint32_t af[4][4], bf[8][2];
            #pragma unroll
            for (int mt = 0; mt < 4; mt++) {
                const int r = wm + mt * 16 + gid;
                af[mt][0] = __float_as_uint(As[r * SROW + kc]);
                af[mt][1] = __float_as_uint(As[(r + 8) * SROW + kc]);
                af[mt][2] = __float_as_uint(As[r * SROW + kc + 4]);
                af[mt][3] = __float_as_uint(As[(r + 8) * SROW + kc + 4]);
            }
            #pragma unroll
            for (int nt = 0; nt < 8; nt++) {
                const int c = wn + nt * 8 + gid;
                bf[nt][0] = __float_as_uint(Bs[c * SROW + kc]);
                bf[nt][1] = __float_as_uint(Bs[c * SROW + kc + 4]);
            }
            #pragma unroll
            for (int mt = 0; mt < 4; mt++)
                #pragma unroll
                for (int nt = 0; nt < 8; nt++)
                    mma_tf32(acc[mt][nt], af[mt], bf[nt]);
        }
        __syncthreads();
    }

    // ---- epilogue ----
    #pragma unroll
    for (int nt = 0; nt < 8; nt++) {
        const int nl = wn + nt * 8 + tig * 2;
        if (G1) {
            float2 bb = *(const float2*)(bias + (size_t)e * D_FF + n0 + nl);
            #pragma unroll
            for (int mt = 0; mt < 4; mt++) {
                int mA = m0 + wm + mt * 16 + gid;
                if (mA < cnt) {
                    float2 v;
                    v.x = gelu_exact(acc[mt][nt][0] + bb.x);
                    v.y = gelu_exact(acc[mt][nt][1] + bb.y);
                    *(float2*)(g_H + ((size_t)e * N_TOKENS + mA) * D_FF + n0 + nl) = v;
                }
                int mB = mA + 8;
                if (mB < cnt) {
                    float2 v;
                    v.x = gelu_exact(acc[mt][nt][2] + bb.x);
                    v.y = gelu_exact(acc[mt][nt][3] + bb.y);
                    *(float2*)(g_H + ((size_t)e * N_TOKENS + mB) * D_FF + n0 + nl) = v;
                }
            }
        } else {
            float2 bb = *(const float2*)(bias + (size_t)e * D_MODEL + n0 + nl);
            #pragma unroll
            for (int mt = 0; mt < 4; mt++) {
                int mA = m0 + wm + mt * 16 + gid;
                if (mA < cnt) {
                    int tok = stok[wm + mt * 16 + gid];
                    float2 xv = *(const float2*)(resid + (size_t)tok * D_MODEL + n0 + nl);
                    float2 v;
                    v.x = acc[mt][nt][0] + bb.x + xv.x;
                    v.y = acc[mt][nt][1] + bb.y + xv.y;
                    *(float2*)(g_Z + ((size_t)e * N_TOKENS + mA) * D_MODEL + n0 + nl) = v;
                }
                int mB = mA + 8;
                if (mB < cnt) {
                    int tok = stok[wm + mt * 16 + gid + 8];
                    float2 xv = *(const float2*)(resid + (size_t)tok * D_MODEL + n0 + nl);
                    float2 v;
                    v.x = acc[mt][nt][2] + bb.x + xv.x;
                    v.y = acc[mt][nt][3] + bb.y + xv.y;
                    *(float2*)(g_Z + ((size_t)e * N_TOKENS + mB) * D_MODEL + n0 + nl) = v;
                }
            }
        }
    }
}

// ---------------- LayerNorm + gamma/beta + weighted scatter-add ----------------
__global__ void __launch_bounds__(256) ln_kernel(const float* __restrict__ gamma,
                                                 const float* __restrict__ beta,
                                                 float* __restrict__ out) {
    const int e    = blockIdx.y;
    const int slot = blockIdx.x;
    if (slot >= g_cnt[e]) return;

    const int   tok = g_tok[e * N_TOKENS + slot];
    const float w   = g_wgt[e * N_TOKENS + slot];
    const float* z  = g_Z + ((size_t)e * N_TOKENS + slot) * D_MODEL;

    const int tid  = threadIdx.x;
    const int lane = tid & 31, warp = tid >> 5;

    __shared__ float red1[8];
    __shared__ float red2[8];

    float4 v = ((const float4*)z)[tid];

    float s = v.x + v.y + v.z + v.w;
    #pragma unroll
    for (int o = 16; o; o >>= 1) s += __shfl_xor_sync(0xffffffffu, s, o);
    if (lane == 0) red1[warp] = s;
    __syncthreads();
    float tot = 0.f;
    #pragma unroll
    for (int i = 0; i < 8; i++) tot += red1[i];
    const float mu = tot * (1.0f / D_MODEL);

    float dx = v.x - mu, dy = v.y - mu, dz = v.z - mu, dw = v.w - mu;
    float sq = dx * dx + dy * dy + dz * dz + dw * dw;
    #pragma unroll
    for (int o = 16; o; o >>= 1) sq += __shfl_xor_sync(0xffffffffu, sq, o);
    if (lane == 0) red2[warp] = sq;
    __syncthreads();
    float tot2 = 0.f;
    #pragma unroll
    for (int i = 0; i < 8; i++) tot2 += red2[i];
    const float var  = tot2 * (1.0f / D_MODEL);
    const float rstd = rsqrtf(var + 1e-6f);

    float4 g  = ((const float4*)(gamma + (size_t)e * D_MODEL))[tid];
    float4 bb = ((const float4*)(beta  + (size_t)e * D_MODEL))[tid];

    float* o = out + (size_t)tok * D_MODEL + tid * 4;
    atomicAdd(o + 0, w * (dx * rstd * g.x + bb.x));
    atomicAdd(o + 1, w * (dy * rstd * g.y + bb.y));
    atomicAdd(o + 2, w * (dz * rstd * g.z + bb.z));
    atomicAdd(o + 3, w * (dw * rstd * g.w + bb.w));
}

// ---------------- launch ----------------
extern "C" void kernel_launch(void* const* d_in, const int* in_sizes, int n_in,
                              void* d_out, int out_size) {
    const float* x      = (const float*)d_in[0];
    const float* gate_w = (const float*)d_in[1];
    const float* w1     = (const float*)d_in[2];
    const float* b1     = (const float*)d_in[3];
    const float* w2     = (const float*)d_in[4];
    const float* b2     = (const float*)d_in[5];
    const float* gamma  = (const float*)d_in[6];
    const float* beta   = (const float*)d_in[7];

    float* hptr = nullptr;
    cudaGetSymbolAddress((void**)&hptr, g_H);

    cudaFuncSetAttribute(moe_gemm<D_MODEL, true>,
                         cudaFuncAttributeMaxDynamicSharedMemorySize, SMEM_DYN);
    cudaFuncSetAttribute(moe_gemm<D_FF, false>,
                         cudaFuncAttributeMaxDynamicSharedMemorySize, SMEM_DYN);

    cudaMemsetAsync(d_out, 0, (size_t)out_size * sizeof(float), 0);
    init_counts_kernel<<<1, 32>>>();
    gate_kernel<<<N_TOKENS / 8, 256>>>(x, gate_w);

    dim3 g1(D_FF / BN, N_TOKENS / 128, N_EXPERTS);
    moe_gemm<D_MODEL, true><<<g1, 256, SMEM_DYN>>>(x, w1, b1, nullptr);

    dim3 g2(D_MODEL / BN, N_TOKENS / 128, N_EXPERTS);
    moe_gemm<D_FF, false><<<g2, 256, SMEM_DYN>>>(hptr, w2, b2, x);

    dim3 g3(N_TOKENS, N_EXPERTS);
    ln_kernel<<<g3, 256>>>(gamma, beta, (float*)d_out);
}

// round 6
// speedup vs baseline: 1.0492x; 1.0492x over previous
#include <cuda_runtime.h>
#include <math.h>
#include <stdint.h>

#define N_TOKENS 16384
#define D_MODEL  1024
#define D_FF     2048
#define N_EXPERTS 4

// ---------------- scratch (device globals; no allocation allowed) ----------------
__device__ int   g_cnt[N_EXPERTS];
__device__ int   g_tok[N_EXPERTS * N_TOKENS];
__device__ int   g_eidx[2 * N_TOKENS];   // per-token expert ids (top2)
__device__ int   g_slot[2 * N_TOKENS];   // per-token slot within expert list
__device__ float g_wsm [2 * N_TOKENS];   // per-token softmax weights
__device__ float g_H[(size_t)N_EXPERTS * N_TOKENS * D_FF];     // 512 MB
__device__ float g_Z[(size_t)N_EXPERTS * N_TOKENS * D_MODEL];  // 256 MB

__device__ __forceinline__ float gelu_exact(float v) {
    return 0.5f * v * (1.0f + erff(v * 0.70710678118654752440f));
}

__device__ __forceinline__ void mma_tf32(float c[4], const uint32_t a[4], const uint32_t b[2]) {
    asm volatile(
        "mma.sync.aligned.m16n8k8.row.col.f32.tf32.tf32.f32 "
        "{%0,%1,%2,%3}, {%4,%5,%6,%7}, {%8,%9}, {%0,%1,%2,%3};"
        : "+f"(c[0]), "+f"(c[1]), "+f"(c[2]), "+f"(c[3])
        : "r"(a[0]), "r"(a[1]), "r"(a[2]), "r"(a[3]), "r"(b[0]), "r"(b[1]));
}

__device__ __forceinline__ uint32_t smem_u32(const void* p) {
    uint32_t a;
    asm("{ .reg .u64 t; cvta.to.shared.u64 t, %1; cvt.u32.u64 %0, t; }" : "=r"(a) : "l"(p));
    return a;
}
__device__ __forceinline__ void cpasync16(uint32_t dst, const void* src) {
    asm volatile("cp.async.cg.shared.global [%0], [%1], 16;" :: "r"(dst), "l"(src));
}
__device__ __forceinline__ void cp_commit() {
    asm volatile("cp.async.commit_group;" ::: "memory");
}
__device__ __forceinline__ void cp_wait1() {
    asm volatile("cp.async.wait_group 1;" ::: "memory");
}
__device__ __forceinline__ void cp_wait0() {
    asm volatile("cp.async.wait_group 0;" ::: "memory");
}

// ---------------- init ----------------
__global__ void init_counts_kernel() {
    if (threadIdx.x < N_EXPERTS) g_cnt[threadIdx.x] = 0;
}

// ---------------- gating: scores, top-2, softmax, compaction ----------------
__global__ void __launch_bounds__(256) gate_kernel(const float* __restrict__ x,
                                                   const float* __restrict__ gate_w) {
    __shared__ float sgw[N_EXPERTS * D_MODEL];
    const int tid = threadIdx.x;
    for (int i = tid; i < N_EXPERTS * D_MODEL; i += 256) sgw[i] = gate_w[i];
    __syncthreads();

    const int warp = tid >> 5, lane = tid & 31;
    const int tok = blockIdx.x * 8 + warp;
    if (tok >= N_TOKENS) return;

    const float* xr = x + (size_t)tok * D_MODEL;
    float acc0 = 0.f, acc1 = 0.f, acc2 = 0.f, acc3 = 0.f;
    for (int k = lane; k < D_MODEL; k += 32) {
        float xv = xr[k];
        acc0 += xv * sgw[0 * D_MODEL + k];
        acc1 += xv * sgw[1 * D_MODEL + k];
        acc2 += xv * sgw[2 * D_MODEL + k];
        acc3 += xv * sgw[3 * D_MODEL + k];
    }
    #pragma unroll
    for (int o = 16; o; o >>= 1) {
        acc0 += __shfl_xor_sync(0xffffffffu, acc0, o);
        acc1 += __shfl_xor_sync(0xffffffffu, acc1, o);
        acc2 += __shfl_xor_sync(0xffffffffu, acc2, o);
        acc3 += __shfl_xor_sync(0xffffffffu, acc3, o);
    }
    if (lane == 0) {
        float s[4] = {acc0, acc1, acc2, acc3};
        int i0 = 0;
        #pragma unroll
        for (int e = 1; e < 4; e++) if (s[e] > s[i0]) i0 = e;
        int i1 = -1;
        #pragma unroll
        for (int e = 0; e < 4; e++) {
            if (e == i0) continue;
            if (i1 < 0 || s[e] > s[i1]) i1 = e;
        }
        float t  = expf(s[i1] - s[i0]);
        float p0 = 1.0f / (1.0f + t);
        float p1 = t / (1.0f + t);

        int sl0 = atomicAdd(&g_cnt[i0], 1);
        g_tok[i0 * N_TOKENS + sl0] = tok;
        int sl1 = atomicAdd(&g_cnt[i1], 1);
        g_tok[i1 * N_TOKENS + sl1] = tok;

        g_eidx[2 * tok + 0] = i0;  g_slot[2 * tok + 0] = sl0;  g_wsm[2 * tok + 0] = p0;
        g_eidx[2 * tok + 1] = i1;  g_slot[2 * tok + 1] = sl1;  g_wsm[2 * tok + 1] = p1;
    }
}

// ======================= TF32 tensor-core GEMMs (cp.async pipelined) =======================
// Tile 128x128, BK=32, 256 threads = 8 warps (2 M x 4 N), warp tile 64x32.
// 3-stage cp.async pipeline, smem row stride 36 floats (conflict-free fragment LDS).
#define BK 32
#define SROW 36
#define STAGES 3
#define A_STAGE_F (128 * SROW)                 // floats
#define STAGE_F   (2 * A_STAGE_F)              // A + B
#define SMEM_DYN  (STAGES * STAGE_F * 4)       // bytes = 110592

template<int KDIM, bool G1>
__global__ void __launch_bounds__(256, 2) moe_gemm(
    const float* __restrict__ Asrc, const float* __restrict__ W,
    const float* __restrict__ bias, const float* __restrict__ resid)
{
    const int e   = blockIdx.z;
    const int cnt = g_cnt[e];
    const int m0  = blockIdx.y * 128;
    if (m0 >= cnt) return;
    const int n0  = blockIdx.x * 128;

    extern __shared__ float smem[];
    __shared__ int stok[128];

    const int tid = threadIdx.x;
    if (tid < 128) {
        int m = m0 + tid;
        stok[tid] = g_tok[e * N_TOKENS + (m < cnt ? m : cnt - 1)];
    }
    __syncthreads();

    // ---- loader mapping: 4 A-chunks + 4 B-chunks of 16B per thread per stage ----
    const int cj4  = (tid & 7) * 4;   // float offset within a 32-float row
    const int row0 = tid >> 3;        // 0..31

    const float* aptr[4];
    const float* bptr[4];
    uint32_t off16[4];
    #pragma unroll
    for (int i = 0; i < 4; i++) {
        const int row = row0 + 32 * i;
        if (G1) {
            aptr[i] = Asrc + (size_t)stok[row] * KDIM + cj4;
        } else {
            int mr = m0 + row; if (mr >= cnt) mr = cnt - 1;
            aptr[i] = Asrc + ((size_t)e * N_TOKENS + mr) * KDIM + cj4;
        }
        bptr[i] = W + (size_t)e * ((size_t)D_FF * D_MODEL) + (size_t)(n0 + row) * KDIM + cj4;
        off16[i] = (uint32_t)(row * SROW + cj4) * 4u;
    }

    const uint32_t sbase = smem_u32(smem);

    auto issue = [&](int t, int s) {
        const int kt = t * BK;
        const uint32_t sa = sbase + (uint32_t)s * (STAGE_F * 4);
        const uint32_t sb = sa + A_STAGE_F * 4;
        #pragma unroll
        for (int i = 0; i < 4; i++) {
            cpasync16(sa + off16[i], aptr[i] + kt);
            cpasync16(sb + off16[i], bptr[i] + kt);
        }
    };

    // ---- compute mapping ----
    const int warp = tid >> 5, lane = tid & 31;
    const int wm = (warp & 1) * 64;
    const int wn = (warp >> 1) * 32;
    const int gid = lane >> 2, tig = lane & 3;

    float acc[4][4][4];
    #pragma unroll
    for (int mt = 0; mt < 4; mt++)
        #pragma unroll
        for (int nt = 0; nt < 4; nt++)
            #pragma unroll
            for (int r = 0; r < 4; r++) acc[mt][nt][r] = 0.f;

    constexpr int T = KDIM / BK;

    issue(0, 0); cp_commit();
    issue(1, 1); cp_commit();

    for (int t = 0; t < T; t++) {
        const int s = t % STAGES;
        if (t + 2 < T) cp_wait1(); else cp_wait0();
        __syncthreads();
        if (t + 2 < T) { issue(t + 2, (t + 2) % STAGES); cp_commit(); }

        const float* As = smem + s * STAGE_F;
        const float* Bs = As + A_STAGE_F;

        #pragma unroll
        for (int ks = 0; ks < 4; ks++) {
            const int kc = ks * 8 + tig;
            uint32_t af[4][4], bf[4][2];
            #pragma unroll
            for (int mt = 0; mt < 4; mt++) {
                const int r = wm + mt * 16 + gid;
                af[mt][0] = __float_as_uint(As[r * SROW + kc]);
                af[mt][1] = __float_as_uint(As[(r + 8) * SROW + kc]);
                af[mt][2] = __float_as_uint(As[r * SROW + kc + 4]);
                af[mt][3] = __float_as_uint(As[(r + 8) * SROW + kc + 4]);
            }
            #pragma unroll
            for (int nt = 0; nt < 4; nt++) {
                const int c = wn + nt * 8 + gid;
                bf[nt][0] = __float_as_uint(Bs[c * SROW + kc]);
                bf[nt][1] = __float_as_uint(Bs[c * SROW + kc + 4]);
            }
            #pragma unroll
            for (int mt = 0; mt < 4; mt++)
                #pragma unroll
                for (int nt = 0; nt < 4; nt++)
                    mma_tf32(acc[mt][nt], af[mt], bf[nt]);
        }
        __syncthreads();
    }

    // ---- epilogue ----
    #pragma unroll
    for (int nt = 0; nt < 4; nt++) {
        const int nl = wn + nt * 8 + tig * 2;
        if (G1) {
            float2 bb = *(const float2*)(bias + (size_t)e * D_FF + n0 + nl);
            #pragma unroll
            for (int mt = 0; mt < 4; mt++) {
                int mA = m0 + wm + mt * 16 + gid;
                if (mA < cnt) {
                    float2 v;
                    v.x = gelu_exact(acc[mt][nt][0] + bb.x);
                    v.y = gelu_exact(acc[mt][nt][1] + bb.y);
                    *(float2*)(g_H + ((size_t)e * N_TOKENS + mA) * D_FF + n0 + nl) = v;
                }
                int mB = mA + 8;
                if (mB < cnt) {
                    float2 v;
                    v.x = gelu_exact(acc[mt][nt][2] + bb.x);
                    v.y = gelu_exact(acc[mt][nt][3] + bb.y);
                    *(float2*)(g_H + ((size_t)e * N_TOKENS + mB) * D_FF + n0 + nl) = v;
                }
            }
        } else {
            float2 bb = *(const float2*)(bias + (size_t)e * D_MODEL + n0 + nl);
            #pragma unroll
            for (int mt = 0; mt < 4; mt++) {
                int mA = m0 + wm + mt * 16 + gid;
                if (mA < cnt) {
                    int tok = stok[wm + mt * 16 + gid];
                    float2 xv = *(const float2*)(resid + (size_t)tok * D_MODEL + n0 + nl);
                    float2 v;
                    v.x = acc[mt][nt][0] + bb.x + xv.x;
                    v.y = acc[mt][nt][1] + bb.y + xv.y;
                    *(float2*)(g_Z + ((size_t)e * N_TOKENS + mA) * D_MODEL + n0 + nl) = v;
                }
                int mB = mA + 8;
                if (mB < cnt) {
                    int tok = stok[wm + mt * 16 + gid + 8];
                    float2 xv = *(const float2*)(resid + (size_t)tok * D_MODEL + n0 + nl);
                    float2 v;
                    v.x = acc[mt][nt][2] + bb.x + xv.x;
                    v.y = acc[mt][nt][3] + bb.y + xv.y;
                    *(float2*)(g_Z + ((size_t)e * N_TOKENS + mB) * D_MODEL + n0 + nl) = v;
                }
            }
        }
    }
}

// -------- LayerNorm: one block per token, both experts, direct write (no atomics) --------
__global__ void __launch_bounds__(256) ln_kernel(const float* __restrict__ gamma,
                                                 const float* __restrict__ beta,
                                                 float* __restrict__ out) {
    const int tok = blockIdx.x;
    const int tid  = threadIdx.x;
    const int lane = tid & 31, warp = tid >> 5;

    __shared__ float red1[8];
    __shared__ float red2[8];

    float4 osum = make_float4(0.f, 0.f, 0.f, 0.f);

    #pragma unroll
    for (int j = 0; j < 2; j++) {
        const int   e    = g_eidx[2 * tok + j];
        const int   slot = g_slot[2 * tok + j];
        const float w    = g_wsm [2 * tok + j];
        const float* z   = g_Z + ((size_t)e * N_TOKENS + slot) * D_MODEL;

        float4 v = ((const float4*)z)[tid];

        float s = v.x + v.y + v.z + v.w;
        #pragma unroll
        for (int o = 16; o; o >>= 1) s += __shfl_xor_sync(0xffffffffu, s, o);
        if (lane == 0) red1[warp] = s;
        __syncthreads();
        float tot = 0.f;
        #pragma unroll
        for (int i = 0; i < 8; i++) tot += red1[i];
        const float mu = tot * (1.0f / D_MODEL);

        float dx = v.x - mu, dy = v.y - mu, dz = v.z - mu, dw = v.w - mu;
        float sq = dx * dx + dy * dy + dz * dz + dw * dw;
        #pragma unroll
        for (int o = 16; o; o >>= 1) sq += __shfl_xor_sync(0xffffffffu, sq, o);
        if (lane == 0) red2[warp] = sq;
        __syncthreads();
        float tot2 = 0.f;
        #pragma unroll
        for (int i = 0; i < 8; i++) tot2 += red2[i];
        const float var  = tot2 * (1.0f / D_MODEL);
        const float rstd = rsqrtf(var + 1e-6f);

        float4 g  = ((const float4*)(gamma + (size_t)e * D_MODEL))[tid];
        float4 bb = ((const float4*)(beta  + (size_t)e * D_MODEL))[tid];

        osum.x += w * (dx * rstd * g.x + bb.x);
        osum.y += w * (dy * rstd * g.y + bb.y);
        osum.z += w * (dz * rstd * g.z + bb.z);
        osum.w += w * (dw * rstd * g.w + bb.w);
        __syncthreads();   // protect red1/red2 reuse
    }

    ((float4*)(out + (size_t)tok * D_MODEL))[tid] = osum;
}

// ---------------- launch ----------------
extern "C" void kernel_launch(void* const* d_in, const int* in_sizes, int n_in,
                              void* d_out, int out_size) {
    const float* x      = (const float*)d_in[0];
    const float* gate_w = (const float*)d_in[1];
    const float* w1     = (const float*)d_in[2];
    const float* b1     = (const float*)d_in[3];
    const float* w2     = (const float*)d_in[4];
    const float* b2     = (const float*)d_in[5];
    const float* gamma  = (const float*)d_in[6];
    const float* beta   = (const float*)d_in[7];

    float* hptr = nullptr;
    cudaGetSymbolAddress((void**)&hptr, g_H);

    cudaFuncSetAttribute(moe_gemm<D_MODEL, true>,
                         cudaFuncAttributeMaxDynamicSharedMemorySize, SMEM_DYN);
    cudaFuncSetAttribute(moe_gemm<D_FF, false>,
                         cudaFuncAttributeMaxDynamicSharedMemorySize, SMEM_DYN);

    init_counts_kernel<<<1, 32>>>();
    gate_kernel<<<N_TOKENS / 8, 256>>>(x, gate_w);

    dim3 g1(D_FF / 128, N_TOKENS / 128, N_EXPERTS);
    moe_gemm<D_MODEL, true><<<g1, 256, SMEM_DYN>>>(x, w1, b1, nullptr);

    dim3 g2(D_MODEL / 128, N_TOKENS / 128, N_EXPERTS);
    moe_gemm<D_FF, false><<<g2, 256, SMEM_DYN>>>(hptr, w2, b2, x);

    ln_kernel<<<N_TOKENS, 256>>>(gamma, beta, (float*)d_out);
}